// round 12
// baseline (speedup 1.0000x reference)
#include <cuda_runtime.h>
#include <cuda_bf16.h>
#include <cstdint>
#include <stdint.h>
#include <math.h>

#define NN 100000
#define NE 800000
#define DD 96
#define D4 (DD/4)
#define SCAN_B 1024
#define NB_SCAN ((NN + SCAN_B - 1) / SCAN_B)
#define TM 128
#define NT ((NN + TM - 1) / TM)      // 782

#define PADB 208
#define AH_OFF 0
#define AL_OFF (AH_OFF + TM * PADB)
#define WH_OFF (AL_OFF + TM * PADB)
#define WL_OFF (WH_OFF + DD * PADB)
#define SMEM_TOTAL (WL_OFF + DD * PADB)      // 93184

// ---- scratch (static device globals) ----
__device__ __align__(16) float g_h[(size_t)NN * DD];    // h' layer1 out / h2 layer2 out
__device__ __align__(16) float g_h2[(size_t)NN * DD];   // layer-2 GEMM out (gather2 source)
__device__ __align__(16) __nv_bfloat16 g_w1h[DD * DD], g_w1l[DD * DD];
__device__ __align__(16) __nv_bfloat16 g_w2h[DD * DD], g_w2l[DD * DD];
__device__ int   g_deg[NN];
__device__ float g_dinv[NN];
__device__ int   g_rowptr[NN + 1];
__device__ int   g_cursor[NN];
__device__ int   g_csr_src[NE];
__device__ int   g_blocksums[NB_SCAN];

__device__ __forceinline__ uint32_t smem_u32(const void* p) {
    uint32_t a;
    asm("{ .reg .u64 t; cvta.to.shared.u64 t, %1; cvt.u32.u64 %0, t; }" : "=r"(a) : "l"(p));
    return a;
}
__device__ __forceinline__ void ldsm4(uint32_t* r, uint32_t addr) {
    asm volatile("ldmatrix.sync.aligned.m8n8.x4.shared.b16 {%0,%1,%2,%3}, [%4];"
        : "=r"(r[0]), "=r"(r[1]), "=r"(r[2]), "=r"(r[3]) : "r"(addr));
}
__device__ __forceinline__ void ldsm4t(uint32_t* r, uint32_t addr) {
    asm volatile("ldmatrix.sync.aligned.m8n8.x4.trans.shared.b16 {%0,%1,%2,%3}, [%4];"
        : "=r"(r[0]), "=r"(r[1]), "=r"(r[2]), "=r"(r[3]) : "r"(addr));
}
__device__ __forceinline__ void mma16816(float* c, const uint32_t* a, uint32_t b0, uint32_t b1) {
    asm volatile("mma.sync.aligned.m16n8k16.row.col.f32.bf16.bf16.f32 "
        "{%0,%1,%2,%3}, {%4,%5,%6,%7}, {%8,%9}, {%0,%1,%2,%3};"
        : "+f"(c[0]), "+f"(c[1]), "+f"(c[2]), "+f"(c[3])
        : "r"(a[0]), "r"(a[1]), "r"(a[2]), "r"(a[3]), "r"(b0), "r"(b1));
}

// ---------------- degree / norm / CSR build ----------------
__global__ void count_deg_kernel(const int* __restrict__ dst) {
    int e = blockIdx.x * blockDim.x + threadIdx.x;
    if (e < NE) { int d = dst[e]; if ((unsigned)d < NN) atomicAdd(&g_deg[d], 1); }
}
__global__ void scan_block_kernel() {   // block scan + dinv (fused)
    __shared__ int sh[SCAN_B];
    int i = blockIdx.x * SCAN_B + threadIdx.x;
    int v = (i < NN) ? g_deg[i] : 0;
    if (i < NN) g_dinv[i] = rsqrtf((float)(v + 1));
    sh[threadIdx.x] = v;
    __syncthreads();
#pragma unroll
    for (int ofs = 1; ofs < SCAN_B; ofs <<= 1) {
        int t = (threadIdx.x >= ofs) ? sh[threadIdx.x - ofs] : 0;
        __syncthreads();
        sh[threadIdx.x] += t;
        __syncthreads();
    }
    if (i < NN) g_rowptr[i] = sh[threadIdx.x] - v;
    if (threadIdx.x == SCAN_B - 1) g_blocksums[blockIdx.x] = sh[SCAN_B - 1];
}
__global__ void scan_add_kernel() {     // per-block reduce of block-sum prefix
    __shared__ int red[128];
    int t = threadIdx.x, bid = blockIdx.x;
    int v = 0;
    if (t < 128) {
        for (int k = t; k < bid; k += 128) v += g_blocksums[k];
        red[t] = v;
    }
    __syncthreads();
#pragma unroll
    for (int o = 64; o > 0; o >>= 1) {
        if (t < o) red[t] += red[t + o];
        __syncthreads();
    }
    int base = red[0];
    int i = bid * SCAN_B + t;
    if (i < NN) {
        int r = g_rowptr[i] + base;
        g_rowptr[i] = r;
        g_cursor[i] = r;
    }
    if (i == 0) g_rowptr[NN] = NE;
}
__global__ void bin_edges_kernel(const int* __restrict__ ei) {
    int e = blockIdx.x * blockDim.x + threadIdx.x;
    if (e >= NE) return;
    int s = ei[e], d = ei[NE + e];
    if ((unsigned)s >= NN || (unsigned)d >= NN) return;
    g_csr_src[atomicAdd(&g_cursor[d], 1)] = s;
}

// ---------------- weight conversion ----------------
__global__ void convert_w2x(const float* __restrict__ W1, const float* __restrict__ W2) {
    int idx = blockIdx.x * blockDim.x + threadIdx.x;
    if (idx >= 2 * DD * DD) return;
    int which = idx >= DD * DD;
    int i = idx - which * DD * DD;
    float v = which ? W2[i] : W1[i];
    __nv_bfloat16 h = __float2bfloat16(v);
    __nv_bfloat16 l = __float2bfloat16(v - __bfloat162float(h));
    if (which) { g_w2h[i] = h; g_w2l[i] = l; }
    else       { g_w1h[i] = h; g_w1l[i] = l; }
}

// ---------------- GEMM1: h'[r,:] = (X @ W1) * dinv[r]  (fp32 in, bf16-split MMA) ----------------
__global__ void __launch_bounds__(256, 2)
mma_gemm1(const float* __restrict__ Xf,
          const __nv_bfloat16* __restrict__ Wh, const __nv_bfloat16* __restrict__ Wl,
          float* __restrict__ out) {
    extern __shared__ __align__(16) char smem[];
    const int tid = threadIdx.x, w = tid >> 5, lane = tid & 31;

    {
        int r = tid >> 1, half = tid & 1;
        int gr = blockIdx.x * TM + r;
        uint2* dH = (uint2*)(smem + AH_OFF + r * PADB + half * 96);
        uint2* dL = (uint2*)(smem + AL_OFF + r * PADB + half * 96);
        if (gr < NN) {
            const float4* s = (const float4*)(Xf + (size_t)gr * DD) + half * 12;
#pragma unroll
            for (int i = 0; i < 12; i++) {
                float4 v = s[i];
                __nv_bfloat162 h0 = __floats2bfloat162_rn(v.x, v.y);
                __nv_bfloat162 h1 = __floats2bfloat162_rn(v.z, v.w);
                __nv_bfloat162 l0 = __floats2bfloat162_rn(v.x - __bfloat162float(h0.x),
                                                          v.y - __bfloat162float(h0.y));
                __nv_bfloat162 l1 = __floats2bfloat162_rn(v.z - __bfloat162float(h1.x),
                                                          v.w - __bfloat162float(h1.y));
                dH[i] = make_uint2(*(uint32_t*)&h0, *(uint32_t*)&h1);
                dL[i] = make_uint2(*(uint32_t*)&l0, *(uint32_t*)&l1);
            }
        } else {
            uint2 z = make_uint2(0, 0);
#pragma unroll
            for (int i = 0; i < 12; i++) { dH[i] = z; dL[i] = z; }
        }
    }
    if (tid < DD) {
        uint4* d = (uint4*)(smem + WH_OFF + tid * PADB);
        const uint4* s = (const uint4*)(Wh + (size_t)tid * DD);
#pragma unroll
        for (int i = 0; i < 12; i++) d[i] = s[i];
    } else if (tid >= 128 && tid < 128 + DD) {
        int r = tid - 128;
        uint4* d = (uint4*)(smem + WL_OFF + r * PADB);
        const uint4* s = (const uint4*)(Wl + (size_t)r * DD);
#pragma unroll
        for (int i = 0; i < 12; i++) d[i] = s[i];
    }
    __syncthreads();

    const uint32_t sb = smem_u32(smem);
    float acc[12][4];
#pragma unroll
    for (int t = 0; t < 12; t++)
#pragma unroll
        for (int q = 0; q < 4; q++) acc[t][q] = 0.f;

    const uint32_t aH = sb + AH_OFF + (w * 16 + (lane & 15)) * PADB + (lane >> 4) * 16;
    const uint32_t aL = sb + AL_OFF + (w * 16 + (lane & 15)) * PADB + (lane >> 4) * 16;
    const uint32_t bH = sb + WH_OFF + (lane & 15) * PADB + (lane >> 4) * 16;
    const uint32_t bL = sb + WL_OFF + (lane & 15) * PADB + (lane >> 4) * 16;

#pragma unroll
    for (int ks = 0; ks < 6; ks++) {
        uint32_t ah[4], al[4];
        ldsm4(ah, aH + ks * 32);
        ldsm4(al, aL + ks * 32);
#pragma unroll
        for (int nb = 0; nb < 6; nb++) {
            uint32_t bh[4], bl[4];
            ldsm4t(bh, bH + ks * 16 * PADB + nb * 32);
            ldsm4t(bl, bL + ks * 16 * PADB + nb * 32);
            mma16816(acc[2 * nb],     ah, bh[0], bh[1]);
            mma16816(acc[2 * nb],     ah, bl[0], bl[1]);
            mma16816(acc[2 * nb],     al, bh[0], bh[1]);
            mma16816(acc[2 * nb + 1], ah, bh[2], bh[3]);
            mma16816(acc[2 * nb + 1], ah, bl[2], bl[3]);
            mma16816(acc[2 * nb + 1], al, bh[2], bh[3]);
        }
    }

    int r0 = blockIdx.x * TM + w * 16 + (lane >> 2);
    int c0 = (lane & 3) * 2;
    float d0 = (r0 < NN) ? g_dinv[r0] : 0.f;
    float d1 = (r0 + 8 < NN) ? g_dinv[r0 + 8] : 0.f;
#pragma unroll
    for (int nt = 0; nt < 12; nt++) {
        int col = nt * 8 + c0;
        if (r0 < NN)
            *(float2*)(out + (size_t)r0 * DD + col) = make_float2(acc[nt][0] * d0, acc[nt][1] * d0);
        if (r0 + 8 < NN)
            *(float2*)(out + (size_t)(r0 + 8) * DD + col) = make_float2(acc[nt][2] * d1, acc[nt][3] * d1);
    }
}

// ---------------- FUSED: gather1+BN+split (into smem) -> GEMM2 -> h2' ----------------
__global__ void __launch_bounds__(256, 2)
fused_g1_gemm2(const float* __restrict__ h, const float* __restrict__ bias,
               const float* __restrict__ gamma, const float* __restrict__ beta,
               const float* __restrict__ mean,  const float* __restrict__ var,
               const __nv_bfloat16* __restrict__ Wh, const __nv_bfloat16* __restrict__ Wl,
               float* __restrict__ out) {
    extern __shared__ __align__(16) char smem[];
    const int tid = threadIdx.x, w = tid >> 5, lane = tid & 31;
    const int base = blockIdx.x * TM;

    // stage W2 tiles
    if (tid < DD) {
        uint4* d = (uint4*)(smem + WH_OFF + tid * PADB);
        const uint4* s = (const uint4*)(Wh + (size_t)tid * DD);
#pragma unroll
        for (int i = 0; i < 12; i++) d[i] = s[i];
    } else if (tid >= 128 && tid < 128 + DD) {
        int r = tid - 128;
        uint4* d = (uint4*)(smem + WL_OFF + r * PADB);
        const uint4* s = (const uint4*)(Wl + (size_t)r * DD);
#pragma unroll
        for (int i = 0; i < 12; i++) d[i] = s[i];
    }

    // phase 1: gather 16 nodes per warp, write bf16 hi/lo A-tiles to smem
    if (lane < D4) {
        float4 bb = ((const float4*)bias)[lane];
        float4 G  = ((const float4*)gamma)[lane];
        float4 B  = ((const float4*)beta)[lane];
        float4 M  = ((const float4*)mean)[lane];
        float4 V  = ((const float4*)var)[lane];
        float rs_x = rsqrtf(V.x + 1e-5f), rs_y = rsqrtf(V.y + 1e-5f);
        float rs_z = rsqrtf(V.z + 1e-5f), rs_w = rsqrtf(V.w + 1e-5f);

        for (int i = 0; i < 16; i++) {
            int r = w * 16 + i;
            int n = base + r;
            uint2 oH = make_uint2(0, 0), oL = make_uint2(0, 0);
            if (n < NN) {
                float4 acc = ((const float4*)(h + (size_t)n * DD))[lane];
                int off = g_rowptr[n], end = g_rowptr[n + 1];
                for (; off + 3 < end; off += 4) {
                    int s0 = g_csr_src[off],     s1 = g_csr_src[off + 1];
                    int s2 = g_csr_src[off + 2], s3 = g_csr_src[off + 3];
                    float4 v0 = ((const float4*)(h + (size_t)s0 * DD))[lane];
                    float4 v1 = ((const float4*)(h + (size_t)s1 * DD))[lane];
                    float4 v2 = ((const float4*)(h + (size_t)s2 * DD))[lane];
                    float4 v3 = ((const float4*)(h + (size_t)s3 * DD))[lane];
                    v0.x += v1.x; v0.y += v1.y; v0.z += v1.z; v0.w += v1.w;
                    v2.x += v3.x; v2.y += v3.y; v2.z += v3.z; v2.w += v3.w;
                    acc.x += v0.x + v2.x; acc.y += v0.y + v2.y;
                    acc.z += v0.z + v2.z; acc.w += v0.w + v2.w;
                }
                for (; off < end; off++) {
                    int s0 = g_csr_src[off];
                    float4 v0 = ((const float4*)(h + (size_t)s0 * DD))[lane];
                    acc.x += v0.x; acc.y += v0.y; acc.z += v0.z; acc.w += v0.w;
                }
                float dn = g_dinv[n];
                acc.x = fmaf(acc.x, dn, bb.x);
                acc.y = fmaf(acc.y, dn, bb.y);
                acc.z = fmaf(acc.z, dn, bb.z);
                acc.w = fmaf(acc.w, dn, bb.w);
                acc.x = acc.x >= 0.f ? acc.x : 0.05f * acc.x;
                acc.y = acc.y >= 0.f ? acc.y : 0.05f * acc.y;
                acc.z = acc.z >= 0.f ? acc.z : 0.05f * acc.z;
                acc.w = acc.w >= 0.f ? acc.w : 0.05f * acc.w;
                acc.x = fmaf((acc.x - M.x) * rs_x, G.x, B.x);
                acc.y = fmaf((acc.y - M.y) * rs_y, G.y, B.y);
                acc.z = fmaf((acc.z - M.z) * rs_z, G.z, B.z);
                acc.w = fmaf((acc.w - M.w) * rs_w, G.w, B.w);
                __nv_bfloat162 h0 = __floats2bfloat162_rn(acc.x, acc.y);
                __nv_bfloat162 h1 = __floats2bfloat162_rn(acc.z, acc.w);
                __nv_bfloat162 l0 = __floats2bfloat162_rn(acc.x - __bfloat162float(h0.x),
                                                          acc.y - __bfloat162float(h0.y));
                __nv_bfloat162 l1 = __floats2bfloat162_rn(acc.z - __bfloat162float(h1.x),
                                                          acc.w - __bfloat162float(h1.y));
                oH = make_uint2(*(uint32_t*)&h0, *(uint32_t*)&h1);
                oL = make_uint2(*(uint32_t*)&l0, *(uint32_t*)&l1);
            }
            *(uint2*)(smem + AH_OFF + r * PADB + lane * 8) = oH;
            *(uint2*)(smem + AL_OFF + r * PADB + lane * 8) = oL;
        }
    }
    __syncthreads();

    // phase 2: MMA
    const uint32_t sb = smem_u32(smem);
    float acc[12][4];
#pragma unroll
    for (int t = 0; t < 12; t++)
#pragma unroll
        for (int q = 0; q < 4; q++) acc[t][q] = 0.f;

    const uint32_t aH = sb + AH_OFF + (w * 16 + (lane & 15)) * PADB + (lane >> 4) * 16;
    const uint32_t aL = sb + AL_OFF + (w * 16 + (lane & 15)) * PADB + (lane >> 4) * 16;
    const uint32_t bH = sb + WH_OFF + (lane & 15) * PADB + (lane >> 4) * 16;
    const uint32_t bL = sb + WL_OFF + (lane & 15) * PADB + (lane >> 4) * 16;

#pragma unroll
    for (int ks = 0; ks < 6; ks++) {
        uint32_t ah[4], al[4];
        ldsm4(ah, aH + ks * 32);
        ldsm4(al, aL + ks * 32);
#pragma unroll
        for (int nb = 0; nb < 6; nb++) {
            uint32_t bh[4], bl[4];
            ldsm4t(bh, bH + ks * 16 * PADB + nb * 32);
            ldsm4t(bl, bL + ks * 16 * PADB + nb * 32);
            mma16816(acc[2 * nb],     ah, bh[0], bh[1]);
            mma16816(acc[2 * nb],     ah, bl[0], bl[1]);
            mma16816(acc[2 * nb],     al, bh[0], bh[1]);
            mma16816(acc[2 * nb + 1], ah, bh[2], bh[3]);
            mma16816(acc[2 * nb + 1], ah, bl[2], bl[3]);
            mma16816(acc[2 * nb + 1], al, bh[2], bh[3]);
        }
    }

    int r0 = base + w * 16 + (lane >> 2);
    int c0 = (lane & 3) * 2;
    float d0 = (r0 < NN) ? g_dinv[r0] : 0.f;
    float d1 = (r0 + 8 < NN) ? g_dinv[r0 + 8] : 0.f;
#pragma unroll
    for (int nt = 0; nt < 12; nt++) {
        int col = nt * 8 + c0;
        if (r0 < NN)
            *(float2*)(out + (size_t)r0 * DD + col) = make_float2(acc[nt][0] * d0, acc[nt][1] * d0);
        if (r0 + 8 < NN)
            *(float2*)(out + (size_t)(r0 + 8) * DD + col) = make_float2(acc[nt][2] * d1, acc[nt][3] * d1);
    }
}

// ---------------- final pull aggregation (layer 2) ----------------
__global__ void __launch_bounds__(256)
gather_final(const float* __restrict__ h, const float* __restrict__ bias,
             float* __restrict__ outf) {
    int n    = (blockIdx.x * blockDim.x + threadIdx.x) >> 5;
    int lane = threadIdx.x & 31;
    if (n >= NN || lane >= D4) return;

    float4 acc = ((const float4*)(h + (size_t)n * DD))[lane];
    int off = g_rowptr[n], end = g_rowptr[n + 1];
    for (; off + 3 < end; off += 4) {
        int s0 = g_csr_src[off],     s1 = g_csr_src[off + 1];
        int s2 = g_csr_src[off + 2], s3 = g_csr_src[off + 3];
        float4 v0 = ((const float4*)(h + (size_t)s0 * DD))[lane];
        float4 v1 = ((const float4*)(h + (size_t)s1 * DD))[lane];
        float4 v2 = ((const float4*)(h + (size_t)s2 * DD))[lane];
        float4 v3 = ((const float4*)(h + (size_t)s3 * DD))[lane];
        v0.x += v1.x; v0.y += v1.y; v0.z += v1.z; v0.w += v1.w;
        v2.x += v3.x; v2.y += v3.y; v2.z += v3.z; v2.w += v3.w;
        acc.x += v0.x + v2.x; acc.y += v0.y + v2.y;
        acc.z += v0.z + v2.z; acc.w += v0.w + v2.w;
    }
    for (; off < end; off++) {
        int s0 = g_csr_src[off];
        float4 v0 = ((const float4*)(h + (size_t)s0 * DD))[lane];
        acc.x += v0.x; acc.y += v0.y; acc.z += v0.z; acc.w += v0.w;
    }
    float dn = g_dinv[n];
    float4 bb = ((const float4*)bias)[lane];
    acc.x = fmaf(acc.x, dn, bb.x);
    acc.y = fmaf(acc.y, dn, bb.y);
    acc.z = fmaf(acc.z, dn, bb.z);
    acc.w = fmaf(acc.w, dn, bb.w);
    ((float4*)(outf + (size_t)n * DD))[lane] = acc;
}

// ---------------- launcher ----------------
extern "C" void kernel_launch(void* const* d_in, const int* in_sizes, int n_in,
                              void* d_out, int out_size) {
    const float* X     = (const float*)d_in[0];
    const int*   ei    = (const int*)d_in[1];
    const float* W1    = (const float*)d_in[2];
    const float* b1    = (const float*)d_in[3];
    const float* W2    = (const float*)d_in[4];
    const float* b2    = (const float*)d_in[5];
    const float* gamma = (const float*)d_in[6];
    const float* beta  = (const float*)d_in[7];
    const float* mean  = (const float*)d_in[8];
    const float* var   = (const float*)d_in[9];
    float* out = (float*)d_out;

    void* p;
    cudaGetSymbolAddress(&p, g_h);   float* h  = (float*)p;
    cudaGetSymbolAddress(&p, g_h2);  float* h2 = (float*)p;
    cudaGetSymbolAddress(&p, g_w1h); __nv_bfloat16* w1h = (__nv_bfloat16*)p;
    cudaGetSymbolAddress(&p, g_w1l); __nv_bfloat16* w1l = (__nv_bfloat16*)p;
    cudaGetSymbolAddress(&p, g_w2h); __nv_bfloat16* w2h = (__nv_bfloat16*)p;
    cudaGetSymbolAddress(&p, g_w2l); __nv_bfloat16* w2l = (__nv_bfloat16*)p;
    void* degp; cudaGetSymbolAddress(&degp, g_deg);

    cudaFuncSetAttribute(mma_gemm1, cudaFuncAttributeMaxDynamicSharedMemorySize, SMEM_TOTAL);
    cudaFuncSetAttribute(fused_g1_gemm2, cudaFuncAttributeMaxDynamicSharedMemorySize, SMEM_TOTAL);

    static cudaStream_t s2 = nullptr;
    static cudaEvent_t evA = nullptr, evD = nullptr, evG = nullptr;
    if (!s2) {
        cudaStreamCreate(&s2);
        cudaEventCreateWithFlags(&evA, cudaEventDisableTiming);
        cudaEventCreateWithFlags(&evD, cudaEventDisableTiming);
        cudaEventCreateWithFlags(&evG, cudaEventDisableTiming);
    }

    const int TPB = 256;
    int edgeBlocks = (NE + TPB - 1) / TPB;
    int wBlocks    = (2 * DD * DD + TPB - 1) / TPB;
    int gathBlocks = (NN + 7) / 8;

    // ---- stream 0: degree -> scan(+dinv) -> add -> bin ----
    cudaEventRecord(evA, 0);
    cudaMemsetAsync(degp, 0, NN * sizeof(int), 0);
    count_deg_kernel<<<edgeBlocks, TPB>>>(ei + NE);
    scan_block_kernel<<<NB_SCAN, SCAN_B>>>();      // also writes dinv
    cudaEventRecord(evD, 0);
    scan_add_kernel<<<NB_SCAN, SCAN_B>>>();
    bin_edges_kernel<<<edgeBlocks, TPB>>>(ei);

    // ---- stream s2: weight conversion + layer-1 GEMM (overlaps scan/bin) ----
    cudaStreamWaitEvent(s2, evA, 0);
    convert_w2x<<<wBlocks, TPB, 0, s2>>>(W1, W2);
    cudaStreamWaitEvent(s2, evD, 0);
    mma_gemm1<<<NT, 256, SMEM_TOTAL, s2>>>(X, w1h, w1l, h);
    cudaEventRecord(evG, s2);

    // ---- join: fused gather1+GEMM2 (needs CSR + h'), then final gather ----
    cudaStreamWaitEvent(0, evG, 0);
    fused_g1_gemm2<<<NT, 256, SMEM_TOTAL>>>(h, b1, gamma, beta, mean, var, w2h, w2l, h2);
    gather_final<<<gathBlocks, TPB>>>(h2, b2, out);
}

// round 14
// speedup vs baseline: 1.1642x; 1.1642x over previous
#include <cuda_runtime.h>
#include <cuda_bf16.h>
#include <cstdint>
#include <stdint.h>
#include <math.h>

#define NN 100000
#define NE 800000
#define DD 96
#define D4 (DD/4)
#define SCAN_B 1024
#define NB_SCAN ((NN + SCAN_B - 1) / SCAN_B)
#define TM 128
#define NT ((NN + TM - 1) / TM)      // 782

#define PADB 208
#define AH_OFF 0
#define AL_OFF (AH_OFF + TM * PADB)
#define WH_OFF (AL_OFF + TM * PADB)
#define WL_OFF (WH_OFF + DD * PADB)
#define SMEM_TOTAL (WL_OFF + DD * PADB)      // 93184

// ---- scratch (static device globals) ----
__device__ __align__(16) float g_h[(size_t)NN * DD];            // h' = (xW)*dinv[row]
__device__ __align__(16) __nv_bfloat16 g_xh[(size_t)NN * DD];
__device__ __align__(16) __nv_bfloat16 g_xl[(size_t)NN * DD];
__device__ __align__(16) __nv_bfloat16 g_w1h[DD * DD], g_w1l[DD * DD];
__device__ __align__(16) __nv_bfloat16 g_w2h[DD * DD], g_w2l[DD * DD];
__device__ int   g_deg[NN];
__device__ float g_dinv[NN];
__device__ int   g_rowptr[NN + 1];
__device__ int   g_cursor[NN];
__device__ int   g_csr_src[NE];
__device__ int   g_blocksums[NB_SCAN];

__device__ __forceinline__ uint32_t smem_u32(const void* p) {
    uint32_t a;
    asm("{ .reg .u64 t; cvta.to.shared.u64 t, %1; cvt.u32.u64 %0, t; }" : "=r"(a) : "l"(p));
    return a;
}
__device__ __forceinline__ void ldsm4(uint32_t* r, uint32_t addr) {
    asm volatile("ldmatrix.sync.aligned.m8n8.x4.shared.b16 {%0,%1,%2,%3}, [%4];"
        : "=r"(r[0]), "=r"(r[1]), "=r"(r[2]), "=r"(r[3]) : "r"(addr));
}
__device__ __forceinline__ void ldsm4t(uint32_t* r, uint32_t addr) {
    asm volatile("ldmatrix.sync.aligned.m8n8.x4.trans.shared.b16 {%0,%1,%2,%3}, [%4];"
        : "=r"(r[0]), "=r"(r[1]), "=r"(r[2]), "=r"(r[3]) : "r"(addr));
}
__device__ __forceinline__ void mma16816(float* c, const uint32_t* a, uint32_t b0, uint32_t b1) {
    asm volatile("mma.sync.aligned.m16n8k16.row.col.f32.bf16.bf16.f32 "
        "{%0,%1,%2,%3}, {%4,%5,%6,%7}, {%8,%9}, {%0,%1,%2,%3};"
        : "+f"(c[0]), "+f"(c[1]), "+f"(c[2]), "+f"(c[3])
        : "r"(a[0]), "r"(a[1]), "r"(a[2]), "r"(a[3]), "r"(b0), "r"(b1));
}

// ---------------- degree / norm / CSR build ----------------
__global__ void count_deg_kernel(const int* __restrict__ dst) {
    int e = blockIdx.x * blockDim.x + threadIdx.x;
    if (e < NE) { int d = dst[e]; if ((unsigned)d < NN) atomicAdd(&g_deg[d], 1); }
}
__global__ void scan_block_kernel() {   // block scan + dinv (fused)
    __shared__ int sh[SCAN_B];
    int i = blockIdx.x * SCAN_B + threadIdx.x;
    int v = (i < NN) ? g_deg[i] : 0;
    if (i < NN) g_dinv[i] = rsqrtf((float)(v + 1));
    sh[threadIdx.x] = v;
    __syncthreads();
#pragma unroll
    for (int ofs = 1; ofs < SCAN_B; ofs <<= 1) {
        int t = (threadIdx.x >= ofs) ? sh[threadIdx.x - ofs] : 0;
        __syncthreads();
        sh[threadIdx.x] += t;
        __syncthreads();
    }
    if (i < NN) g_rowptr[i] = sh[threadIdx.x] - v;
    if (threadIdx.x == SCAN_B - 1) g_blocksums[blockIdx.x] = sh[SCAN_B - 1];
}
__global__ void scan_add_kernel() {     // per-block reduce of block-sum prefix
    __shared__ int red[128];
    int t = threadIdx.x, bid = blockIdx.x;
    int v = 0;
    if (t < 128) {
        for (int k = t; k < bid; k += 128) v += g_blocksums[k];
        red[t] = v;
    }
    __syncthreads();
#pragma unroll
    for (int o = 64; o > 0; o >>= 1) {
        if (t < o) red[t] += red[t + o];
        __syncthreads();
    }
    int base = red[0];
    int i = bid * SCAN_B + t;
    if (i < NN) {
        int r = g_rowptr[i] + base;
        g_rowptr[i] = r;
        g_cursor[i] = r;
    }
    if (i == 0) g_rowptr[NN] = NE;
}
__global__ void bin_edges_kernel(const int* __restrict__ ei) {
    int e = blockIdx.x * blockDim.x + threadIdx.x;
    if (e >= NE) return;
    int s = ei[e], d = ei[NE + e];
    if ((unsigned)s >= NN || (unsigned)d >= NN) return;
    g_csr_src[atomicAdd(&g_cursor[d], 1)] = s;
}

// ---------------- weight conversion (both layers, one launch) ----------------
__global__ void convert_w2x(const float* __restrict__ W1, const float* __restrict__ W2) {
    int idx = blockIdx.x * blockDim.x + threadIdx.x;
    if (idx >= 2 * DD * DD) return;
    int which = idx >= DD * DD;
    int i = idx - which * DD * DD;
    float v = which ? W2[i] : W1[i];
    __nv_bfloat16 h = __float2bfloat16(v);
    __nv_bfloat16 l = __float2bfloat16(v - __bfloat162float(h));
    if (which) { g_w2h[i] = h; g_w2l[i] = l; }
    else       { g_w1h[i] = h; g_w1l[i] = l; }
}

// ---------------- mma.sync bf16-split GEMM: out[r,:] = (x @ W) * dinv[r] ----------------
template <int SPLIT>
__global__ void __launch_bounds__(256, 2)
mma_gemm(const float* __restrict__ Xf,
         const __nv_bfloat16* __restrict__ Xh, const __nv_bfloat16* __restrict__ Xl,
         const __nv_bfloat16* __restrict__ Wh, const __nv_bfloat16* __restrict__ Wl,
         float* __restrict__ out) {
    extern __shared__ __align__(16) char smem[];
    const int tid = threadIdx.x, w = tid >> 5, lane = tid & 31;

    {
        int r = tid >> 1, half = tid & 1;
        int gr = blockIdx.x * TM + r;
        if (SPLIT) {
            uint2* dH = (uint2*)(smem + AH_OFF + r * PADB + half * 96);
            uint2* dL = (uint2*)(smem + AL_OFF + r * PADB + half * 96);
            if (gr < NN) {
                const float4* s = (const float4*)(Xf + (size_t)gr * DD) + half * 12;
#pragma unroll
                for (int i = 0; i < 12; i++) {
                    float4 v = s[i];
                    __nv_bfloat162 h0 = __floats2bfloat162_rn(v.x, v.y);
                    __nv_bfloat162 h1 = __floats2bfloat162_rn(v.z, v.w);
                    __nv_bfloat162 l0 = __floats2bfloat162_rn(v.x - __bfloat162float(h0.x),
                                                              v.y - __bfloat162float(h0.y));
                    __nv_bfloat162 l1 = __floats2bfloat162_rn(v.z - __bfloat162float(h1.x),
                                                              v.w - __bfloat162float(h1.y));
                    dH[i] = make_uint2(*(uint32_t*)&h0, *(uint32_t*)&h1);
                    dL[i] = make_uint2(*(uint32_t*)&l0, *(uint32_t*)&l1);
                }
            } else {
                uint2 z = make_uint2(0, 0);
#pragma unroll
                for (int i = 0; i < 12; i++) { dH[i] = z; dL[i] = z; }
            }
        } else {
            uint4* dH = (uint4*)(smem + AH_OFF + r * PADB + half * 96);
            uint4* dL = (uint4*)(smem + AL_OFF + r * PADB + half * 96);
            if (gr < NN) {
                const uint4* sH = (const uint4*)(Xh + (size_t)gr * DD) + half * 6;
                const uint4* sL = (const uint4*)(Xl + (size_t)gr * DD) + half * 6;
#pragma unroll
                for (int i = 0; i < 6; i++) { dH[i] = sH[i]; dL[i] = sL[i]; }
            } else {
                uint4 z = make_uint4(0, 0, 0, 0);
#pragma unroll
                for (int i = 0; i < 6; i++) { dH[i] = z; dL[i] = z; }
            }
        }
    }
    if (tid < DD) {
        uint4* d = (uint4*)(smem + WH_OFF + tid * PADB);
        const uint4* s = (const uint4*)(Wh + (size_t)tid * DD);
#pragma unroll
        for (int i = 0; i < 12; i++) d[i] = s[i];
    } else if (tid >= 128 && tid < 128 + DD) {
        int r = tid - 128;
        uint4* d = (uint4*)(smem + WL_OFF + r * PADB);
        const uint4* s = (const uint4*)(Wl + (size_t)r * DD);
#pragma unroll
        for (int i = 0; i < 12; i++) d[i] = s[i];
    }
    __syncthreads();

    const uint32_t sb = smem_u32(smem);
    float acc[12][4];
#pragma unroll
    for (int t = 0; t < 12; t++)
#pragma unroll
        for (int q = 0; q < 4; q++) acc[t][q] = 0.f;

    const uint32_t aH = sb + AH_OFF + (w * 16 + (lane & 15)) * PADB + (lane >> 4) * 16;
    const uint32_t aL = sb + AL_OFF + (w * 16 + (lane & 15)) * PADB + (lane >> 4) * 16;
    const uint32_t bH = sb + WH_OFF + (lane & 15) * PADB + (lane >> 4) * 16;
    const uint32_t bL = sb + WL_OFF + (lane & 15) * PADB + (lane >> 4) * 16;

#pragma unroll
    for (int ks = 0; ks < 6; ks++) {
        uint32_t ah[4], al[4];
        ldsm4(ah, aH + ks * 32);
        ldsm4(al, aL + ks * 32);
#pragma unroll
        for (int nb = 0; nb < 6; nb++) {
            uint32_t bh[4], bl[4];
            ldsm4t(bh, bH + ks * 16 * PADB + nb * 32);
            ldsm4t(bl, bL + ks * 16 * PADB + nb * 32);
            mma16816(acc[2 * nb],     ah, bh[0], bh[1]);
            mma16816(acc[2 * nb],     ah, bl[0], bl[1]);
            mma16816(acc[2 * nb],     al, bh[0], bh[1]);
            mma16816(acc[2 * nb + 1], ah, bh[2], bh[3]);
            mma16816(acc[2 * nb + 1], ah, bl[2], bl[3]);
            mma16816(acc[2 * nb + 1], al, bh[2], bh[3]);
        }
    }

    int r0 = blockIdx.x * TM + w * 16 + (lane >> 2);
    int c0 = (lane & 3) * 2;
    float d0 = (r0 < NN) ? g_dinv[r0] : 0.f;
    float d1 = (r0 + 8 < NN) ? g_dinv[r0 + 8] : 0.f;
#pragma unroll
    for (int nt = 0; nt < 12; nt++) {
        int col = nt * 8 + c0;
        if (r0 < NN)
            *(float2*)(out + (size_t)r0 * DD + col) = make_float2(acc[nt][0] * d0, acc[nt][1] * d0);
        if (r0 + 8 < NN)
            *(float2*)(out + (size_t)(r0 + 8) * DD + col) = make_float2(acc[nt][2] * d1, acc[nt][3] * d1);
    }
}

// ---------------- pull aggregation (one warp per node, 24 active lanes, 8-edge unroll) ----------------
template <int BN>
__global__ void __launch_bounds__(256)
gather_nodes(const float* __restrict__ h, const float* __restrict__ bias,
             const float* __restrict__ gamma, const float* __restrict__ beta,
             const float* __restrict__ mean,  const float* __restrict__ var,
             float* __restrict__ outf) {
    int n    = (blockIdx.x * blockDim.x + threadIdx.x) >> 5;
    int lane = threadIdx.x & 31;
    if (n >= NN || lane >= D4) return;

    float4 acc = ((const float4*)(h + (size_t)n * DD))[lane];

    int off = g_rowptr[n], end = g_rowptr[n + 1];
    // 8-edge unrolled (mean degree = 8): 8 row-loads in flight
    for (; off + 7 < end; off += 8) {
        int s[8];
#pragma unroll
        for (int k = 0; k < 8; k++) s[k] = g_csr_src[off + k];
        float4 v[8];
#pragma unroll
        for (int k = 0; k < 8; k++) v[k] = ((const float4*)(h + (size_t)s[k] * DD))[lane];
#pragma unroll
        for (int k = 0; k < 8; k++) {
            acc.x += v[k].x; acc.y += v[k].y; acc.z += v[k].z; acc.w += v[k].w;
        }
    }
    for (; off + 3 < end; off += 4) {
        int s0 = g_csr_src[off],     s1 = g_csr_src[off + 1];
        int s2 = g_csr_src[off + 2], s3 = g_csr_src[off + 3];
        float4 v0 = ((const float4*)(h + (size_t)s0 * DD))[lane];
        float4 v1 = ((const float4*)(h + (size_t)s1 * DD))[lane];
        float4 v2 = ((const float4*)(h + (size_t)s2 * DD))[lane];
        float4 v3 = ((const float4*)(h + (size_t)s3 * DD))[lane];
        acc.x += v0.x + v1.x + v2.x + v3.x;
        acc.y += v0.y + v1.y + v2.y + v3.y;
        acc.z += v0.z + v1.z + v2.z + v3.z;
        acc.w += v0.w + v1.w + v2.w + v3.w;
    }
    for (; off < end; off++) {
        int s0 = g_csr_src[off];
        float4 v0 = ((const float4*)(h + (size_t)s0 * DD))[lane];
        acc.x += v0.x; acc.y += v0.y; acc.z += v0.z; acc.w += v0.w;
    }

    float dn = g_dinv[n];
    float4 bb = ((const float4*)bias)[lane];
    acc.x = fmaf(acc.x, dn, bb.x);
    acc.y = fmaf(acc.y, dn, bb.y);
    acc.z = fmaf(acc.z, dn, bb.z);
    acc.w = fmaf(acc.w, dn, bb.w);

    if (BN) {
        float4 G = ((const float4*)gamma)[lane];
        float4 B = ((const float4*)beta)[lane];
        float4 M = ((const float4*)mean)[lane];
        float4 V = ((const float4*)var)[lane];
        acc.x = acc.x >= 0.f ? acc.x : 0.05f * acc.x;
        acc.y = acc.y >= 0.f ? acc.y : 0.05f * acc.y;
        acc.z = acc.z >= 0.f ? acc.z : 0.05f * acc.z;
        acc.w = acc.w >= 0.f ? acc.w : 0.05f * acc.w;
        acc.x = fmaf((acc.x - M.x) * rsqrtf(V.x + 1e-5f), G.x, B.x);
        acc.y = fmaf((acc.y - M.y) * rsqrtf(V.y + 1e-5f), G.y, B.y);
        acc.z = fmaf((acc.z - M.z) * rsqrtf(V.z + 1e-5f), G.z, B.z);
        acc.w = fmaf((acc.w - M.w) * rsqrtf(V.w + 1e-5f), G.w, B.w);
        __nv_bfloat162 h0 = __floats2bfloat162_rn(acc.x, acc.y);
        __nv_bfloat162 h1 = __floats2bfloat162_rn(acc.z, acc.w);
        __nv_bfloat162 l0 = __floats2bfloat162_rn(acc.x - __bfloat162float(h0.x), acc.y - __bfloat162float(h0.y));
        __nv_bfloat162 l1 = __floats2bfloat162_rn(acc.z - __bfloat162float(h1.x), acc.w - __bfloat162float(h1.y));
        ((uint2*)g_xh)[n * D4 + lane] = make_uint2(*(uint32_t*)&h0, *(uint32_t*)&h1);
        ((uint2*)g_xl)[n * D4 + lane] = make_uint2(*(uint32_t*)&l0, *(uint32_t*)&l1);
    } else {
        ((float4*)(outf + (size_t)n * DD))[lane] = acc;
    }
}

// ---------------- launcher (R10 schedule) ----------------
extern "C" void kernel_launch(void* const* d_in, const int* in_sizes, int n_in,
                              void* d_out, int out_size) {
    const float* X     = (const float*)d_in[0];
    const int*   ei    = (const int*)d_in[1];
    const float* W1    = (const float*)d_in[2];
    const float* b1    = (const float*)d_in[3];
    const float* W2    = (const float*)d_in[4];
    const float* b2    = (const float*)d_in[5];
    const float* gamma = (const float*)d_in[6];
    const float* beta  = (const float*)d_in[7];
    const float* mean  = (const float*)d_in[8];
    const float* var   = (const float*)d_in[9];
    float* out = (float*)d_out;

    void* p;
    cudaGetSymbolAddress(&p, g_h);   float* h = (float*)p;
    cudaGetSymbolAddress(&p, g_xh);  __nv_bfloat16* xh = (__nv_bfloat16*)p;
    cudaGetSymbolAddress(&p, g_xl);  __nv_bfloat16* xl = (__nv_bfloat16*)p;
    cudaGetSymbolAddress(&p, g_w1h); __nv_bfloat16* w1h = (__nv_bfloat16*)p;
    cudaGetSymbolAddress(&p, g_w1l); __nv_bfloat16* w1l = (__nv_bfloat16*)p;
    cudaGetSymbolAddress(&p, g_w2h); __nv_bfloat16* w2h = (__nv_bfloat16*)p;
    cudaGetSymbolAddress(&p, g_w2l); __nv_bfloat16* w2l = (__nv_bfloat16*)p;
    void* degp; cudaGetSymbolAddress(&degp, g_deg);

    cudaFuncSetAttribute(mma_gemm<0>, cudaFuncAttributeMaxDynamicSharedMemorySize, SMEM_TOTAL);
    cudaFuncSetAttribute(mma_gemm<1>, cudaFuncAttributeMaxDynamicSharedMemorySize, SMEM_TOTAL);

    static cudaStream_t s2 = nullptr;
    static cudaEvent_t evA = nullptr, evD = nullptr, evG = nullptr;
    if (!s2) {
        cudaStreamCreate(&s2);
        cudaEventCreateWithFlags(&evA, cudaEventDisableTiming);
        cudaEventCreateWithFlags(&evD, cudaEventDisableTiming);
        cudaEventCreateWithFlags(&evG, cudaEventDisableTiming);
    }

    const int TPB = 256;
    int edgeBlocks = (NE + TPB - 1) / TPB;
    int wBlocks    = (2 * DD * DD + TPB - 1) / TPB;
    int gathBlocks = (NN + 7) / 8;

    // ---- stream 0: degree -> scan(+dinv) -> add -> bin ----
    cudaEventRecord(evA, 0);
    cudaMemsetAsync(degp, 0, NN * sizeof(int), 0);
    count_deg_kernel<<<edgeBlocks, TPB>>>(ei + NE);
    scan_block_kernel<<<NB_SCAN, SCAN_B>>>();      // also writes dinv
    cudaEventRecord(evD, 0);
    scan_add_kernel<<<NB_SCAN, SCAN_B>>>();
    bin_edges_kernel<<<edgeBlocks, TPB>>>(ei);

    // ---- stream s2: weight conversion + layer-1 GEMM (overlaps scan/bin) ----
    cudaStreamWaitEvent(s2, evA, 0);
    convert_w2x<<<wBlocks, TPB, 0, s2>>>(W1, W2);
    cudaStreamWaitEvent(s2, evD, 0);
    mma_gemm<1><<<NT, 256, SMEM_TOTAL, s2>>>(X, nullptr, nullptr, w1h, w1l, h);
    cudaEventRecord(evG, s2);

    // ---- join: gather1 needs CSR (stream 0) + h' (s2) ----
    cudaStreamWaitEvent(0, evG, 0);
    gather_nodes<1><<<gathBlocks, TPB>>>(h, b1, gamma, beta, mean, var, nullptr);

    // layer 2 (serial)
    mma_gemm<0><<<NT, 256, SMEM_TOTAL>>>(nullptr, xh, xl, w2h, w2l, h);
    gather_nodes<0><<<gathBlocks, TPB>>>(h, b2, gamma, beta, mean, var, out);
}